// round 1
// baseline (speedup 1.0000x reference)
#include <cuda_runtime.h>
#include <math.h>

#define B_ 8
#define N_ 2048
#define D_ 256
#define TI 64
#define TJ 32

// ---------------- scratch (static device globals; no allocation) -------------
__device__ float g_h [B_ * N_ * D_];   // 16.8 MB: h = x @ W^T
__device__ float g_hl[B_ * N_];
__device__ float g_hr[B_ * N_];
__device__ float g_wl[D_];
__device__ float g_wr[D_];

// ---------------- kernel 0: wl[d] = sum_o a[o]W[o,d], wr likewise -----------
__global__ void k_wlr(const float* __restrict__ W, const float* __restrict__ a)
{
    int d = threadIdx.x;              // 256 threads, 1 block
    float sl = 0.f, sr = 0.f;
    #pragma unroll 8
    for (int o = 0; o < D_; ++o) {
        float w = W[o * D_ + d];      // coalesced across d
        sl = fmaf(a[o],      w, sl);
        sr = fmaf(a[D_ + o], w, sr);
    }
    g_wl[d] = sl;
    g_wr[d] = sr;
}

// ---------------- kernel 1: hl[m] = x[m,:].wl, hr[m] = x[m,:].wr ------------
// one warp per row, 8 rows per 256-thread block
__global__ void k_hlr(const float* __restrict__ x)
{
    int m    = blockIdx.x * 8 + (threadIdx.x >> 5);
    int lane = threadIdx.x & 31;
    const float4* xr  = (const float4*)(x + (size_t)m * D_);
    const float4* wl4 = (const float4*)g_wl;
    const float4* wr4 = (const float4*)g_wr;
    float sl = 0.f, sr = 0.f;
    #pragma unroll
    for (int q = 0; q < 2; ++q) {
        float4 xv = xr [lane + q * 32];
        float4 lv = wl4[lane + q * 32];
        float4 rv = wr4[lane + q * 32];
        sl += xv.x * lv.x + xv.y * lv.y + xv.z * lv.z + xv.w * lv.w;
        sr += xv.x * rv.x + xv.y * rv.y + xv.z * rv.z + xv.w * rv.w;
    }
    #pragma unroll
    for (int off = 16; off > 0; off >>= 1) {
        sl += __shfl_xor_sync(0xFFFFFFFFu, sl, off);
        sr += __shfl_xor_sync(0xFFFFFFFFu, sr, off);
    }
    if (lane == 0) { g_hl[m] = sl; g_hr[m] = sr; }
}

// ---------------- kernel 2: h[m,o] = sum_k x[m,k] * W[o,k] ------------------
// 64x64 block tile, BK=16, 4x4 micro-tile per thread (256 threads)
__global__ __launch_bounds__(256) void k_gemm(const float* __restrict__ x,
                                              const float* __restrict__ W)
{
    __shared__ float xs[16][68];   // transposed tiles, padded
    __shared__ float ws[16][68];

    int m0 = blockIdx.x * 64;
    int o0 = blockIdx.y * 64;
    int t  = threadIdx.x;
    int tx = t & 15;               // output-col group
    int ty = t >> 4;               // output-row group
    int lr = t >> 2;               // load row 0..63
    int lc = (t & 3) * 4;          // load col 0,4,8,12

    const float* xp = x + (size_t)(m0 + lr) * D_ + lc;
    const float* wp = W + (size_t)(o0 + lr) * D_ + lc;

    float acc[4][4];
    #pragma unroll
    for (int r = 0; r < 4; ++r)
        #pragma unroll
        for (int c = 0; c < 4; ++c) acc[r][c] = 0.f;

    for (int k0 = 0; k0 < D_; k0 += 16) {
        float4 xv = *(const float4*)(xp + k0);
        float4 wv = *(const float4*)(wp + k0);
        __syncthreads();                       // previous tile consumed
        xs[lc + 0][lr] = xv.x; xs[lc + 1][lr] = xv.y;
        xs[lc + 2][lr] = xv.z; xs[lc + 3][lr] = xv.w;
        ws[lc + 0][lr] = wv.x; ws[lc + 1][lr] = wv.y;
        ws[lc + 2][lr] = wv.z; ws[lc + 3][lr] = wv.w;
        __syncthreads();
        #pragma unroll
        for (int kk = 0; kk < 16; ++kk) {
            float4 av = *(const float4*)&xs[kk][ty * 4];
            float4 bv = *(const float4*)&ws[kk][tx * 4];
            acc[0][0] = fmaf(av.x, bv.x, acc[0][0]);
            acc[0][1] = fmaf(av.x, bv.y, acc[0][1]);
            acc[0][2] = fmaf(av.x, bv.z, acc[0][2]);
            acc[0][3] = fmaf(av.x, bv.w, acc[0][3]);
            acc[1][0] = fmaf(av.y, bv.x, acc[1][0]);
            acc[1][1] = fmaf(av.y, bv.y, acc[1][1]);
            acc[1][2] = fmaf(av.y, bv.z, acc[1][2]);
            acc[1][3] = fmaf(av.y, bv.w, acc[1][3]);
            acc[2][0] = fmaf(av.z, bv.x, acc[2][0]);
            acc[2][1] = fmaf(av.z, bv.y, acc[2][1]);
            acc[2][2] = fmaf(av.z, bv.z, acc[2][2]);
            acc[2][3] = fmaf(av.z, bv.w, acc[2][3]);
            acc[3][0] = fmaf(av.w, bv.x, acc[3][0]);
            acc[3][1] = fmaf(av.w, bv.y, acc[3][1]);
            acc[3][2] = fmaf(av.w, bv.z, acc[3][2]);
            acc[3][3] = fmaf(av.w, bv.w, acc[3][3]);
        }
    }
    #pragma unroll
    for (int r = 0; r < 4; ++r) {
        float4 o = make_float4(acc[r][0], acc[r][1], acc[r][2], acc[r][3]);
        *(float4*)&g_h[(size_t)(m0 + ty * 4 + r) * D_ + o0 + tx * 4] = o;
    }
}

// ---------------- kernel 3: fused masked-softmax aggregation ----------------
// grid (N/TI, B), 256 threads. Flash-style: no max needed (|e| <~ 10 always,
// exp cannot overflow; masked entries contribute exactly 0).
// Thread identities:
//   p-phase : j = lane, i = w*8 + k        (adj reads fully coalesced)
//   FMA     : rows w*8..w*8+7, cols lane*8..lane*8+7  (8x8 register tile)
__global__ __launch_bounds__(256, 2) void k_aggr(const int* __restrict__ adj,
                                                 float* __restrict__ out)
{
    __shared__ float hs[TJ][D_];       // 32 KB
    __shared__ float ps[TJ][TI + 1];   // pad 65 -> conflict-free writes
    __shared__ float rsum_s[TI];

    int b    = blockIdx.y;
    int i0   = blockIdx.x * TI;
    int t    = threadIdx.x;
    int w    = t >> 5;
    int lane = t & 31;

    const float* hb   = g_h  + (size_t)b * N_ * D_;
    const float* hr_b = g_hr + b * N_;
    const int*   adjb = adj  + ((size_t)b * N_ + i0) * N_;

    float hl_r[8];
    #pragma unroll
    for (int k = 0; k < 8; ++k) hl_r[k] = g_hl[b * N_ + i0 + w * 8 + k];

    float acc[8][8];
    #pragma unroll
    for (int r = 0; r < 8; ++r)
        #pragma unroll
        for (int c = 0; c < 8; ++c) acc[r][c] = 0.f;
    float rsum[8];
    #pragma unroll
    for (int k = 0; k < 8; ++k) rsum[k] = 0.f;

    for (int j0 = 0; j0 < N_; j0 += TJ) {
        // ---- stage global loads into registers (overlaps prior FMA phase) --
        float4 hreg[8];
        #pragma unroll
        for (int q = 0; q < 8; ++q) {
            int idx  = t + q * 256;        // 0..2047 float4 index of tile
            int row  = idx >> 6;           // 64 float4 per 256-wide row
            int col4 = idx & 63;
            hreg[q] = ((const float4*)(hb + (size_t)(j0 + row) * D_))[col4];
        }
        float hrv = hr_b[j0 + lane];

        float pv[8];
        #pragma unroll
        for (int k = 0; k < 8; ++k) {
            int i  = w * 8 + k;
            int av = adjb[(size_t)i * N_ + j0 + lane];   // 128B coalesced
            float e = hl_r[k] + hrv;
            e = (e > 0.f) ? e : 0.2f * e;
            pv[k] = av ? __expf(e) : 0.f;
        }

        __syncthreads();   // previous FMA phase done -> safe to overwrite smem

        #pragma unroll
        for (int q = 0; q < 8; ++q) {
            int idx  = t + q * 256;
            int row  = idx >> 6;
            int col4 = idx & 63;
            ((float4*)&hs[row][0])[col4] = hreg[q];
        }
        #pragma unroll
        for (int k = 0; k < 8; ++k) {
            ps[lane][w * 8 + k] = pv[k];   // bank = (lane + i) % 32: clean
            float s = pv[k];               // lanes hold all 32 j for row i
            s += __shfl_xor_sync(0xFFFFFFFFu, s, 16);
            s += __shfl_xor_sync(0xFFFFFFFFu, s, 8);
            s += __shfl_xor_sync(0xFFFFFFFFu, s, 4);
            s += __shfl_xor_sync(0xFFFFFFFFu, s, 2);
            s += __shfl_xor_sync(0xFFFFFFFFu, s, 1);
            rsum[k] += s;
        }

        __syncthreads();

        // ---- FMA phase: acc[8][8] += P(64x32) @ H(32x256) slice ------------
        #pragma unroll 4
        for (int j = 0; j < TJ; ++j) {
            float4 h0 = *(const float4*)&hs[j][lane * 8];
            float4 h1 = *(const float4*)&hs[j][lane * 8 + 4];
            #pragma unroll
            for (int r = 0; r < 8; ++r) {
                float p = ps[j][w * 8 + r];          // warp-uniform broadcast
                acc[r][0] = fmaf(p, h0.x, acc[r][0]);
                acc[r][1] = fmaf(p, h0.y, acc[r][1]);
                acc[r][2] = fmaf(p, h0.z, acc[r][2]);
                acc[r][3] = fmaf(p, h0.w, acc[r][3]);
                acc[r][4] = fmaf(p, h1.x, acc[r][4]);
                acc[r][5] = fmaf(p, h1.y, acc[r][5]);
                acc[r][6] = fmaf(p, h1.z, acc[r][6]);
                acc[r][7] = fmaf(p, h1.w, acc[r][7]);
            }
        }
    }

    if (lane == 0) {
        #pragma unroll
        for (int k = 0; k < 8; ++k) rsum_s[w * 8 + k] = rsum[k];
    }
    __syncthreads();

    #pragma unroll
    for (int r = 0; r < 8; ++r) {
        float rs  = rsum_s[w * 8 + r];
        float inv = (rs > 0.f) ? (1.f / rs) : 0.f;
        size_t o  = ((size_t)b * N_ + i0 + w * 8 + r) * D_ + lane * 8;
        float4 o0 = make_float4(acc[r][0] * inv, acc[r][1] * inv,
                                acc[r][2] * inv, acc[r][3] * inv);
        float4 o1 = make_float4(acc[r][4] * inv, acc[r][5] * inv,
                                acc[r][6] * inv, acc[r][7] * inv);
        *(float4*)&out[o]     = o0;
        *(float4*)&out[o + 4] = o1;
    }
}

// ---------------------------------------------------------------------------
extern "C" void kernel_launch(void* const* d_in, const int* in_sizes, int n_in,
                              void* d_out, int out_size)
{
    const float* x   = (const float*)d_in[0];   // (8,2048,256) f32
    const int*   adj = (const int*)  d_in[1];   // (8,2048,2048) i32
    const float* W   = (const float*)d_in[2];   // (256,256) f32
    const float* a   = (const float*)d_in[3];   // (1,512) f32
    float*       out = (float*)d_out;           // (8,2048,256) f32

    k_wlr <<<1, 256>>>(W, a);
    k_hlr <<<(B_ * N_) / 8, 256>>>(x);
    k_gemm<<<dim3((B_ * N_) / 64, D_ / 64), 256>>>(x, W);
    k_aggr<<<dim3(N_ / TI, B_), 256>>>(adj, out);
}

// round 3
// speedup vs baseline: 3.2174x; 3.2174x over previous
#include <cuda_runtime.h>
#include <cuda_fp16.h>
#include <math.h>
#include <stdint.h>

#define B_ 8
#define N_ 2048
#define D_ 256

// ---------------------------------------------------------------------------
// helpers (baseline PTX only: cp.async / ldmatrix / mma.sync — compute_100 OK)
// ---------------------------------------------------------------------------
__device__ __forceinline__ unsigned smem_u32(const void* p) {
    unsigned a;
    asm("{ .reg .u64 t; cvta.to.shared.u64 t, %1; cvt.u32.u64 %0, t; }"
        : "=r"(a) : "l"(p));
    return a;
}
__device__ __forceinline__ int SWZ(int x) { return x ^ ((x >> 3) & 0x70); }

#define CP16(dst, src) \
    asm volatile("cp.async.cg.shared.global [%0], [%1], 16;" \
                 :: "r"((unsigned)(dst)), "l"(__cvta_generic_to_global(src)) : "memory")
#define CPC() asm volatile("cp.async.commit_group;" ::: "memory")

#define LDSM4(r0, r1, r2, r3, a) \
    asm volatile("ldmatrix.sync.aligned.m8n8.x4.shared.b16 {%0,%1,%2,%3}, [%4];" \
                 : "=r"(r0), "=r"(r1), "=r"(r2), "=r"(r3) : "r"((unsigned)(a)))

#define MMA(d, a0, a1, a2, a3, b0, b1) \
    asm volatile("mma.sync.aligned.m16n8k16.row.col.f32.f16.f16.f32 " \
                 "{%0,%1,%2,%3}, {%4,%5,%6,%7}, {%8,%9}, {%0,%1,%2,%3};" \
                 : "+f"((d)[0]), "+f"((d)[1]), "+f"((d)[2]), "+f"((d)[3]) \
                 : "r"(a0), "r"(a1), "r"(a2), "r"(a3), "r"(b0), "r"(b1))

// ---------------------------------------------------------------------------
// device globals (no allocation allowed)
// ---------------------------------------------------------------------------
__device__ float g_wl[D_];
__device__ float g_wr[D_];
__device__ __align__(16) float2 g_Elp[B_ * N_];   // (exp(hl), exp(0.2 hl))
__device__ __align__(16) float2 g_Erp[B_ * N_];   // (exp(hr), exp(0.2 hr))
__device__ __align__(16) __half g_Whf[D_ * D_];            // W fp16 row-major [o][k]
__device__ __align__(16) __half g_xh [B_ * N_ * D_];       // x fp16 row-major [m][k]
__device__ __align__(128) unsigned char g_ht[B_ * 32 * 32768]; // h^T fp16: [b][jt][d 256][j 64] swizzled

// ---------------- kernel: wl[d] = sum_o a[o]*W[o,d]; wr likewise ------------
__global__ void k_wlr(const float* __restrict__ W, const float* __restrict__ a)
{
    int d = threadIdx.x;
    float sl = 0.f, sr = 0.f;
    #pragma unroll 8
    for (int o = 0; o < D_; ++o) {
        float w = W[o * D_ + d];
        sl = fmaf(a[o],      w, sl);
        sr = fmaf(a[D_ + o], w, sr);
    }
    g_wl[d] = sl;
    g_wr[d] = sr;
}

// ---------------- kernel: W f32 -> fp16 row-major ---------------------------
__global__ void k_wconv(const float* __restrict__ W)
{
    int t = threadIdx.x;                      // 256 threads, 1 block
    const float4* W4 = (const float4*)W;
    __half2* o = (__half2*)g_Whf;
    for (int q = 0; q < 64; ++q) {
        float4 v = W4[t * 64 + q];
        o[t * 128 + q * 2]     = __floats2half2_rn(v.x, v.y);
        o[t * 128 + q * 2 + 1] = __floats2half2_rn(v.z, v.w);
    }
}

// ---------------- kernel: x f32 -> fp16 row-major ---------------------------
__global__ void k_xconv(const float* __restrict__ x)
{
    int i = blockIdx.x * 256 + threadIdx.x;   // 8 elems per thread
    const float4* x4 = (const float4*)x;
    float4 v0 = x4[i * 2], v1 = x4[i * 2 + 1];
    __half2 h0 = __floats2half2_rn(v0.x, v0.y);
    __half2 h1 = __floats2half2_rn(v0.z, v0.w);
    __half2 h2 = __floats2half2_rn(v1.x, v1.y);
    __half2 h3 = __floats2half2_rn(v1.z, v1.w);
    uint4 pk;
    pk.x = *(unsigned*)&h0; pk.y = *(unsigned*)&h1;
    pk.z = *(unsigned*)&h2; pk.w = *(unsigned*)&h3;
    ((uint4*)g_xh)[i] = pk;
}

// ---------------- kernel: hl/hr dots + factored exponentials ----------------
__global__ void k_hlr(const float* __restrict__ x)
{
    int m    = blockIdx.x * 8 + (threadIdx.x >> 5);
    int lane = threadIdx.x & 31;
    const float4* xr  = (const float4*)(x + (size_t)m * D_);
    const float4* wl4 = (const float4*)g_wl;
    const float4* wr4 = (const float4*)g_wr;
    float sl = 0.f, sr = 0.f;
    #pragma unroll
    for (int q = 0; q < 2; ++q) {
        float4 xv = xr [lane + q * 32];
        float4 lv = wl4[lane + q * 32];
        float4 rv = wr4[lane + q * 32];
        sl += xv.x * lv.x + xv.y * lv.y + xv.z * lv.z + xv.w * lv.w;
        sr += xv.x * rv.x + xv.y * rv.y + xv.z * rv.z + xv.w * rv.w;
    }
    #pragma unroll
    for (int off = 16; off > 0; off >>= 1) {
        sl += __shfl_xor_sync(0xFFFFFFFFu, sl, off);
        sr += __shfl_xor_sync(0xFFFFFFFFu, sr, off);
    }
    if (lane == 0) {
        g_Elp[m] = make_float2(expf(sl), expf(0.2f * sl));
        g_Erp[m] = make_float2(expf(sr), expf(0.2f * sr));
    }
}

// ---------------------------------------------------------------------------
// kernel: h^T[d][j] = sum_k W[d][k] x[j][k]  (HMMA), output fp16 swizzled
// CTA: 64 d x 256 j; warps m32 x n64 (wm 0-1, wn 0-3); K loop 4 chunks of 64
// smem: W [4 kc][64][64k] 32KB @0,  x double buffer 2x32KB @32768
// ---------------------------------------------------------------------------
__global__ __launch_bounds__(256) void k_xh()
{
    extern __shared__ char sm[];
    const int WS = 0, XS = 32768;
    unsigned sb = smem_u32(sm);
    int t = threadIdx.x, l = t & 31, w = t >> 5;
    int wm = w & 1, wn = w >> 1;
    int j0 = blockIdx.x * 256;        // global node row
    int d0 = blockIdx.y * 64;

    // stage W tile (all K) — 2048 x 16B chunks
    #pragma unroll
    for (int q = 0; q < 8; ++q) {
        int idx = t + q * 256;
        int kc = idx >> 9, r = (idx >> 3) & 63, ch = idx & 7;
        CP16(sb + WS + kc * 8192 + SWZ(r * 128 + ch * 16),
             (const char*)g_Whf + (size_t)(d0 + r) * 512 + kc * 128 + ch * 16);
    }
    // prefetch x tile kc=0
    #pragma unroll
    for (int q = 0; q < 8; ++q) {
        int idx = t + q * 256, r = idx >> 3, ch = idx & 7;
        CP16(sb + XS + SWZ(r * 128 + ch * 16),
             (const char*)g_xh + (size_t)(j0 + r) * 512 + ch * 16);
    }
    CPC();

    float acc[8][2][4];
    #pragma unroll
    for (int i = 0; i < 8; ++i)
        #pragma unroll
        for (int m = 0; m < 2; ++m)
            #pragma unroll
            for (int c = 0; c < 4; ++c) acc[i][m][c] = 0.f;

    for (int kc = 0; kc < 4; ++kc) {
        if (kc < 3) {
            unsigned bbuf = sb + XS + ((kc + 1) & 1) * 32768;
            #pragma unroll
            for (int q = 0; q < 8; ++q) {
                int idx = t + q * 256, r = idx >> 3, ch = idx & 7;
                CP16(bbuf + SWZ(r * 128 + ch * 16),
                     (const char*)g_xh + (size_t)(j0 + r) * 512 + (kc + 1) * 128 + ch * 16);
            }
            CPC();
            asm volatile("cp.async.wait_group 1;" ::: "memory");
        } else {
            asm volatile("cp.async.wait_group 0;" ::: "memory");
        }
        __syncthreads();

        unsigned ab = sb + WS + kc * 8192;
        unsigned bb = sb + XS + (kc & 1) * 32768;
        #pragma unroll
        for (int ks = 0; ks < 4; ++ks) {
            unsigned a0[4], a1[4];
            LDSM4(a0[0], a0[1], a0[2], a0[3],
                  ab + SWZ((wm * 32      + (l & 15)) * 128 + ks * 32 + (l >> 4) * 16));
            LDSM4(a1[0], a1[1], a1[2], a1[3],
                  ab + SWZ((wm * 32 + 16 + (l & 15)) * 128 + ks * 32 + (l >> 4) * 16));
            #pragma unroll
            for (int nb2 = 0; nb2 < 4; ++nb2) {
                unsigned b0, b1, b2, b3;
                LDSM4(b0, b1, b2, b3,
                      bb + SWZ((wn * 64 + nb2 * 16 + (l & 15)) * 128 + ks * 32 + (l >> 4) * 16));
                MMA(acc[2*nb2][0],   a0[0], a0[1], a0[2], a0[3], b0, b2);
                MMA(acc[2*nb2][1],   a1[0], a1[1], a1[2], a1[3], b0, b2);
                MMA(acc[2*nb2+1][0], a0[0], a0[1], a0[2], a0[3], b1, b3);
                MMA(acc[2*nb2+1][1], a1[0], a1[1], a1[2], a1[3], b1, b3);
            }
        }
        __syncthreads();
    }

    // epilogue: fp16, into swizzled [b][jt][d][j] tiles
    #pragma unroll
    for (int mi = 0; mi < 2; ++mi) {
        int d = d0 + wm * 32 + mi * 16 + (l >> 2);
        #pragma unroll
        for (int nb = 0; nb < 8; ++nb) {
            int jg = j0 + wn * 64 + nb * 8 + 2 * (l & 3);
            int b  = jg >> 11, jt = (jg & 2047) >> 6, jj = jg & 63;
            unsigned char* tp = g_ht + (size_t)(b * 32 + jt) * 32768;
            __half2 v0 = __floats2half2_rn(acc[nb][mi][0], acc[nb][mi][1]);
            __half2 v1 = __floats2half2_rn(acc[nb][mi][2], acc[nb][mi][3]);
            *(__half2*)(tp + SWZ( d      * 128 + jj * 2)) = v0;
            *(__half2*)(tp + SWZ((d + 8) * 128 + jj * 2)) = v1;
        }
    }
}

// ---------------------------------------------------------------------------
// kernel: fused masked-softmax aggregation (HMMA)
// CTA 512 thr: i-tile M=128, warp tile m32 x n64 (wm 0-3, wn 0-3), K=64 j-tiles
// smem: H 2x32KB @0, P 2x16KB @65536, Elp @98304 (1KB), rsum @99328 (512B)
// ---------------------------------------------------------------------------
__global__ __launch_bounds__(512) void k_aggr(const int* __restrict__ adj,
                                              float* __restrict__ out)
{
    extern __shared__ char sm[];
    const int HS = 0, PS = 65536, ELP = 98304, RSUM = 99328;
    unsigned sb = smem_u32(sm);
    int t = threadIdx.x, l = t & 31, w = t >> 5;
    int wm = w & 3, wn = w >> 2;
    int b = blockIdx.y, i0 = blockIdx.x * 128;
    float2* elp  = (float2*)(sm + ELP);
    float*  rsum = (float*)(sm + RSUM);

    if (t < 128) elp[t] = g_Elp[b * N_ + i0 + t];

    const unsigned char* hsrc = g_ht + (size_t)b * 32 * 32768;
    #pragma unroll
    for (int q = 0; q < 4; ++q) {
        int idx = t + q * 512;
        CP16(sb + HS + idx * 16, hsrc + idx * 16);
    }
    CPC();
    __syncthreads();

    float acc[8][2][4];
    #pragma unroll
    for (int i = 0; i < 8; ++i)
        #pragma unroll
        for (int m = 0; m < 2; ++m)
            #pragma unroll
            for (int c = 0; c < 4; ++c) acc[i][m][c] = 0.f;
    float sacc[2][4] = {{0.f,0.f,0.f,0.f},{0.f,0.f,0.f,0.f}};
    const unsigned ONESH = 0x3C003C00u;

    const float2* erb  = g_Erp + b * N_;
    const int*    adjb = adj + ((size_t)b * N_ + i0) * N_;

    for (int tile = 0; tile < 32; ++tile) {
        int s = tile & 1;
        if (tile < 31) {
            const unsigned char* src = hsrc + (size_t)(tile + 1) * 32768;
            unsigned dstb = sb + HS + ((tile + 1) & 1) * 32768;
            #pragma unroll
            for (int q = 0; q < 4; ++q) {
                int idx = t + q * 512;
                CP16(dstb + idx * 16, src + idx * 16);
            }
            CPC();
        }
        // ---- P tile: p = adj ? (q>1 ? El*Er : El2*Er2) : 0 -----------------
        {
            char* pb = sm + PS + s * 16384;
            #pragma unroll
            for (int rep = 0; rep < 4; ++rep) {
                int idx = t + rep * 512;       // 0..2047
                int row = idx >> 4, c4 = idx & 15;
                int4 av = *(const int4*)(adjb + (size_t)row * N_ + tile * 64 + c4 * 4);
                float2 el = elp[row];
                const float4* e4 = (const float4*)(erb + tile * 64 + c4 * 4);
                float4 ea = e4[0], eb = e4[1];  // (Er0,Er20,Er1,Er21),(Er2,Er22,Er3,Er23)
                float q0 = el.x * ea.x; float p0 = (q0 > 1.f) ? q0 : el.y * ea.y;
                float q1 = el.x * ea.z; float p1 = (q1 > 1.f) ? q1 : el.y * ea.w;
                float q2 = el.x * eb.x; float p2 = (q2 > 1.f) ? q2 : el.y * eb.y;
                float q3 = el.x * eb.z; float p3 = (q3 > 1.f) ? q3 : el.y * eb.w;
                p0 = av.x ? p0 : 0.f;  p1 = av.y ? p1 : 0.f;
                p2 = av.z ? p2 : 0.f;  p3 = av.w ? p3 : 0.f;
                __half2 h01 = __floats2half2_rn(p0, p1);
                __half2 h23 = __floats2half2_rn(p2, p3);
                uint2 pk;
                pk.x = *(unsigned*)&h01;
                pk.y = *(unsigned*)&h23;
                *(uint2*)(pb + SWZ(row * 128 + c4 * 8)) = pk;
            }
        }
        if (tile < 31) asm volatile("cp.async.wait_group 1;" ::: "memory");
        else           asm volatile("cp.async.wait_group 0;" ::: "memory");
        __syncthreads();

        unsigned pbase = sb + PS + s * 16384;
        unsigned hbase = sb + HS + s * 32768;
        #pragma unroll
        for (int ks = 0; ks < 4; ++ks) {
            unsigned a0[4], a1[4];
            LDSM4(a0[0], a0[1], a0[2], a0[3],
                  pbase + SWZ((wm * 32      + (l & 15)) * 128 + ks * 32 + (l >> 4) * 16));
            LDSM4(a1[0], a1[1], a1[2], a1[3],
                  pbase + SWZ((wm * 32 + 16 + (l & 15)) * 128 + ks * 32 + (l >> 4) * 16));
            if (wn == 0) {
                MMA(sacc[0], a0[0], a0[1], a0[2], a0[3], ONESH, ONESH);
                MMA(sacc[1], a1[0], a1[1], a1[2], a1[3], ONESH, ONESH);
            }
            #pragma unroll
            for (int nb2 = 0; nb2 < 4; ++nb2) {
                unsigned b0, b1, b2, b3;
                LDSM4(b0, b1, b2, b3,
                      hbase + SWZ((wn * 64 + nb2 * 16 + (l & 15)) * 128 + ks * 32 + (l >> 4) * 16));
                MMA(acc[2*nb2][0],   a0[0], a0[1], a0[2], a0[3], b0, b2);
                MMA(acc[2*nb2][1],   a1[0], a1[1], a1[2], a1[3], b0, b2);
                MMA(acc[2*nb2+1][0], a0[0], a0[1], a0[2], a0[3], b1, b3);
                MMA(acc[2*nb2+1][1], a1[0], a1[1], a1[2], a1[3], b1, b3);
            }
        }
        __syncthreads();
    }

    // row sums (every column of the ones-mma equals the sum -> no shuffles)
    if (wn == 0 && (l & 3) == 0) {
        int r = wm * 32 + (l >> 2);
        rsum[r]      = sacc[0][0];
        rsum[r + 8]  = sacc[0][2];
        rsum[r + 16] = sacc[1][0];
        rsum[r + 24] = sacc[1][2];
    }
    __syncthreads();

    #pragma unroll
    for (int mi = 0; mi < 2; ++mi) {
        int r0 = wm * 32 + mi * 16 + (l >> 2);
        float s0 = rsum[r0], s1 = rsum[r0 + 8];
        float inv0 = (s0 > 0.f) ? 1.f / s0 : 0.f;
        float inv1 = (s1 > 0.f) ? 1.f / s1 : 0.f;
        float* o0 = out + ((size_t)b * N_ + i0 + r0) * D_;
        float* o1 = o0 + 8 * D_;
        #pragma unroll
        for (int nb = 0; nb < 8; ++nb) {
            int c = wn * 64 + nb * 8 + 2 * (l & 3);
            *(float2*)(o0 + c) = make_float2(acc[nb][mi][0] * inv0,
                                             acc[nb][mi][1] * inv0);
            *(float2*)(o1 + c) = make_float2(acc[nb][mi][2] * inv1,
                                             acc[nb][mi][3] * inv1);
        }
    }
}

// ---------------------------------------------------------------------------
extern "C" void kernel_launch(void* const* d_in, const int* in_sizes, int n_in,
                              void* d_out, int out_size)
{
    const float* x   = (const float*)d_in[0];   // (8,2048,256) f32
    const int*   adj = (const int*)  d_in[1];   // (8,2048,2048) i32
    const float* W   = (const float*)d_in[2];   // (256,256) f32
    const float* a   = (const float*)d_in[3];   // (1,512) f32
    float*       out = (float*)d_out;           // (8,2048,256) f32

    cudaFuncSetAttribute(k_xh,   cudaFuncAttributeMaxDynamicSharedMemorySize, 98304);
    cudaFuncSetAttribute(k_aggr, cudaFuncAttributeMaxDynamicSharedMemorySize, 99840);

    k_wlr  <<<1, 256>>>(W, a);
    k_wconv<<<1, 256>>>(W);
    k_xconv<<<(B_ * N_ * D_) / 2048, 256>>>(x);
    k_hlr  <<<(B_ * N_) / 8, 256>>>(x);
    k_xh   <<<dim3((B_ * N_) / 256, D_ / 64), 256, 98304>>>();
    k_aggr <<<dim3(N_ / 128, B_), 512, 99840>>>(adj, out);
}

// round 4
// speedup vs baseline: 3.7402x; 1.1625x over previous
#include <cuda_runtime.h>
#include <cuda_fp16.h>
#include <math.h>
#include <stdint.h>

#define B_ 8
#define N_ 2048
#define D_ 256

// ---------------------------------------------------------------------------
// helpers (baseline PTX only: cp.async / ldmatrix / mma.sync — compute_100 OK)
// ---------------------------------------------------------------------------
__device__ __forceinline__ unsigned smem_u32(const void* p) {
    unsigned a;
    asm("{ .reg .u64 t; cvta.to.shared.u64 t, %1; cvt.u32.u64 %0, t; }"
        : "=r"(a) : "l"(p));
    return a;
}
__device__ __forceinline__ int SWZ(int x) { return x ^ ((x >> 3) & 0x70); }

#define CP16(dst, src) \
    asm volatile("cp.async.cg.shared.global [%0], [%1], 16;" \
                 :: "r"((unsigned)(dst)), "l"(__cvta_generic_to_global(src)) : "memory")
#define CPC() asm volatile("cp.async.commit_group;" ::: "memory")
#define CPW0() asm volatile("cp.async.wait_group 0;" ::: "memory")
#define CPW1() asm volatile("cp.async.wait_group 1;" ::: "memory")

#define LDSM4(r0, r1, r2, r3, a) \
    asm volatile("ldmatrix.sync.aligned.m8n8.x4.shared.b16 {%0,%1,%2,%3}, [%4];" \
                 : "=r"(r0), "=r"(r1), "=r"(r2), "=r"(r3) : "r"((unsigned)(a)))

#define MMA(d, a0, a1, a2, a3, b0, b1) \
    asm volatile("mma.sync.aligned.m16n8k16.row.col.f32.f16.f16.f32 " \
                 "{%0,%1,%2,%3}, {%4,%5,%6,%7}, {%8,%9}, {%0,%1,%2,%3};" \
                 : "+f"((d)[0]), "+f"((d)[1]), "+f"((d)[2]), "+f"((d)[3]) \
                 : "r"(a0), "r"(a1), "r"(a2), "r"(a3), "r"(b0), "r"(b1))

// ---------------------------------------------------------------------------
// device globals (no allocation allowed)
// ---------------------------------------------------------------------------
__device__ float g_wl[D_];
__device__ float g_wr[D_];
__device__ __align__(16) float2 g_Elp[B_ * N_];   // (exp(hl), exp(0.2 hl))
__device__ __align__(16) float2 g_Erp[B_ * N_];   // (exp(hr), exp(0.2 hr))
__device__ __align__(16) __half g_Whf[D_ * D_];            // W fp16 row-major [o][k]
__device__ __align__(16) __half g_xh [B_ * N_ * D_];       // x fp16 row-major [m][k]
__device__ __align__(128) unsigned char g_ht[B_ * 32 * 32768]; // h^T fp16: [b][jt][d 256][j 64] swizzled

// ---------------- prep: wl/wr vectors + W fp16 conversion -------------------
__global__ void k_prep(const float* __restrict__ W, const float* __restrict__ a)
{
    int d = threadIdx.x;                      // 256 threads, 1 block
    float sl = 0.f, sr = 0.f;
    #pragma unroll 8
    for (int o = 0; o < D_; ++o) {
        float w = W[o * D_ + d];
        sl = fmaf(a[o],      w, sl);
        sr = fmaf(a[D_ + o], w, sr);
    }
    g_wl[d] = sl;
    g_wr[d] = sr;

    const float4* W4 = (const float4*)W;
    __half2* o = (__half2*)g_Whf;
    for (int q = 0; q < 64; ++q) {
        float4 v = W4[d * 64 + q];
        o[d * 128 + q * 2]     = __floats2half2_rn(v.x, v.y);
        o[d * 128 + q * 2 + 1] = __floats2half2_rn(v.z, v.w);
    }
}

// ---------------- k_hlr: hl/hr dots + factored exps + x->fp16 side-write ----
__global__ void k_hlr(const float* __restrict__ x)
{
    int m    = blockIdx.x * 8 + (threadIdx.x >> 5);
    int lane = threadIdx.x & 31;
    const float4* xr  = (const float4*)(x + (size_t)m * D_);
    const float4* wl4 = (const float4*)g_wl;
    const float4* wr4 = (const float4*)g_wr;
    float sl = 0.f, sr = 0.f;
    __half2* xo = (__half2*)(g_xh + (size_t)m * D_);
    #pragma unroll
    for (int q = 0; q < 2; ++q) {
        float4 xv = xr [lane + q * 32];
        float4 lv = wl4[lane + q * 32];
        float4 rv = wr4[lane + q * 32];
        sl += xv.x * lv.x + xv.y * lv.y + xv.z * lv.z + xv.w * lv.w;
        sr += xv.x * rv.x + xv.y * rv.y + xv.z * rv.z + xv.w * rv.w;
        // fp16 side-product (consumed by k_xh)
        xo[(lane + q * 32) * 2]     = __floats2half2_rn(xv.x, xv.y);
        xo[(lane + q * 32) * 2 + 1] = __floats2half2_rn(xv.z, xv.w);
    }
    #pragma unroll
    for (int off = 16; off > 0; off >>= 1) {
        sl += __shfl_xor_sync(0xFFFFFFFFu, sl, off);
        sr += __shfl_xor_sync(0xFFFFFFFFu, sr, off);
    }
    if (lane == 0) {
        g_Elp[m] = make_float2(expf(sl), expf(0.2f * sl));
        g_Erp[m] = make_float2(expf(sr), expf(0.2f * sr));
    }
}

// ---------------------------------------------------------------------------
// k_xh: h^T[d][j] = sum_k W[d][k] x[j][k]  (HMMA), output fp16 swizzled
// CTA: 64 d x 256 j; warps m32 x n64; K loop 4 chunks of 64
// ---------------------------------------------------------------------------
__global__ __launch_bounds__(256) void k_xh()
{
    extern __shared__ char sm[];
    const int WS = 0, XS = 32768;
    unsigned sb = smem_u32(sm);
    int t = threadIdx.x, l = t & 31, w = t >> 5;
    int wm = w & 1, wn = w >> 1;
    int j0 = blockIdx.x * 256;
    int d0 = blockIdx.y * 64;

    #pragma unroll
    for (int q = 0; q < 8; ++q) {
        int idx = t + q * 256;
        int kc = idx >> 9, r = (idx >> 3) & 63, ch = idx & 7;
        CP16(sb + WS + kc * 8192 + SWZ(r * 128 + ch * 16),
             (const char*)g_Whf + (size_t)(d0 + r) * 512 + kc * 128 + ch * 16);
    }
    #pragma unroll
    for (int q = 0; q < 8; ++q) {
        int idx = t + q * 256, r = idx >> 3, ch = idx & 7;
        CP16(sb + XS + SWZ(r * 128 + ch * 16),
             (const char*)g_xh + (size_t)(j0 + r) * 512 + ch * 16);
    }
    CPC();

    float acc[8][2][4];
    #pragma unroll
    for (int i = 0; i < 8; ++i)
        #pragma unroll
        for (int m = 0; m < 2; ++m)
            #pragma unroll
            for (int c = 0; c < 4; ++c) acc[i][m][c] = 0.f;

    for (int kc = 0; kc < 4; ++kc) {
        if (kc < 3) {
            unsigned bbuf = sb + XS + ((kc + 1) & 1) * 32768;
            #pragma unroll
            for (int q = 0; q < 8; ++q) {
                int idx = t + q * 256, r = idx >> 3, ch = idx & 7;
                CP16(bbuf + SWZ(r * 128 + ch * 16),
                     (const char*)g_xh + (size_t)(j0 + r) * 512 + (kc + 1) * 128 + ch * 16);
            }
            CPC();
            CPW1();
        } else {
            CPW0();
        }
        __syncthreads();

        unsigned ab = sb + WS + kc * 8192;
        unsigned bb = sb + XS + (kc & 1) * 32768;
        #pragma unroll
        for (int ks = 0; ks < 4; ++ks) {
            unsigned a0[4], a1[4];
            LDSM4(a0[0], a0[1], a0[2], a0[3],
                  ab + SWZ((wm * 32      + (l & 15)) * 128 + ks * 32 + (l >> 4) * 16));
            LDSM4(a1[0], a1[1], a1[2], a1[3],
                  ab + SWZ((wm * 32 + 16 + (l & 15)) * 128 + ks * 32 + (l >> 4) * 16));
            #pragma unroll
            for (int nb2 = 0; nb2 < 4; ++nb2) {
                unsigned b0, b1, b2, b3;
                LDSM4(b0, b1, b2, b3,
                      bb + SWZ((wn * 64 + nb2 * 16 + (l & 15)) * 128 + ks * 32 + (l >> 4) * 16));
                MMA(acc[2*nb2][0],   a0[0], a0[1], a0[2], a0[3], b0, b2);
                MMA(acc[2*nb2][1],   a1[0], a1[1], a1[2], a1[3], b0, b2);
                MMA(acc[2*nb2+1][0], a0[0], a0[1], a0[2], a0[3], b1, b3);
                MMA(acc[2*nb2+1][1], a1[0], a1[1], a1[2], a1[3], b1, b3);
            }
        }
        __syncthreads();
    }

    #pragma unroll
    for (int mi = 0; mi < 2; ++mi) {
        int d = d0 + wm * 32 + mi * 16 + (l >> 2);
        #pragma unroll
        for (int nb = 0; nb < 8; ++nb) {
            int jg = j0 + wn * 64 + nb * 8 + 2 * (l & 3);
            int b  = jg >> 11, jt = (jg & 2047) >> 6, jj = jg & 63;
            unsigned char* tp = g_ht + (size_t)(b * 32 + jt) * 32768;
            __half2 v0 = __floats2half2_rn(acc[nb][mi][0], acc[nb][mi][1]);
            __half2 v1 = __floats2half2_rn(acc[nb][mi][2], acc[nb][mi][3]);
            *(__half2*)(tp + SWZ( d      * 128 + jj * 2)) = v0;
            *(__half2*)(tp + SWZ((d + 8) * 128 + jj * 2)) = v1;
        }
    }
}

// ---------------------------------------------------------------------------
// k_aggr: fused masked-softmax aggregation (HMMA), fully cp.async-pipelined
// CTA 512 thr: i-tile M=128, warp tile m32 x n64 (wm, wn in 0..3), 32 j-tiles
// smem: H 2x32KB @0 | P 2x16KB @65536 | ADJ 2x32KB @98304 | ER 16KB @163840
//       | ELP 1KB @180224 | RSUM @181248   (total 181760)
// ---------------------------------------------------------------------------
__global__ __launch_bounds__(512) void k_aggr(const int* __restrict__ adj,
                                              float* __restrict__ out)
{
    extern __shared__ char sm[];
    const int HS = 0, PS = 65536, AJ = 98304, ERS = 163840;
    const int ELP = 180224, RSUM = 181248;
    unsigned sb = smem_u32(sm);
    int t = threadIdx.x, l = t & 31, w = t >> 5;
    int wm = w & 3, wn = w >> 2;
    int b = blockIdx.y, i0 = blockIdx.x * 128;
    float2* elp  = (float2*)(sm + ELP);
    float*  rsum = (float*)(sm + RSUM);

    const unsigned char* hsrc = g_ht + (size_t)b * 32 * 32768;
    const int*           adjb = adj + ((size_t)b * N_ + i0) * N_;

    // prologue: group 0 = H(0) + ADJ(0) + Er(whole batch row)
    #pragma unroll
    for (int q = 0; q < 4; ++q) {
        int idx = t + q * 512;
        CP16(sb + HS + idx * 16, hsrc + idx * 16);
    }
    #pragma unroll
    for (int q = 0; q < 4; ++q) {
        int idx = t + q * 512;               // chunk: row=idx>>4, c4=idx&15
        CP16(sb + AJ + idx * 16, adjb + ((size_t)(idx >> 4)) * N_ + (idx & 15) * 4);
    }
    #pragma unroll
    for (int q = 0; q < 2; ++q) {
        int idx = t + q * 512;               // 1024 x 16B = 2048 float2
        CP16(sb + ERS + idx * 16, (const char*)(g_Erp + b * N_) + idx * 16);
    }
    CPC();
    if (t < 128) elp[t] = g_Elp[b * N_ + i0 + t];

    float acc[8][2][4];
    #pragma unroll
    for (int i = 0; i < 8; ++i)
        #pragma unroll
        for (int m = 0; m < 2; ++m)
            #pragma unroll
            for (int c = 0; c < 4; ++c) acc[i][m][c] = 0.f;
    float sacc[2][4] = {{0.f,0.f,0.f,0.f},{0.f,0.f,0.f,0.f}};
    const unsigned ONESH = 0x3C003C00u;

    for (int tile = 0; tile < 32; ++tile) {
        int s = tile & 1;
        CPW0();                      // group(tile) arrived (H + ADJ [+ Er])
        __syncthreads();             // also fences MMA(tile-1) reads

        if (tile < 31) {             // issue group(tile+1) into buffers s^1
            const unsigned char* src = hsrc + (size_t)(tile + 1) * 32768;
            unsigned hdst = sb + HS + (s ^ 1) * 32768;
            unsigned adst = sb + AJ + (s ^ 1) * 32768;
            const int* asrc = adjb + (tile + 1) * 64;
            #pragma unroll
            for (int q = 0; q < 4; ++q) {
                int idx = t + q * 512;
                CP16(hdst + idx * 16, src + idx * 16);
            }
            #pragma unroll
            for (int q = 0; q < 4; ++q) {
                int idx = t + q * 512;
                CP16(adst + idx * 16, asrc + ((size_t)(idx >> 4)) * N_ + (idx & 15) * 4);
            }
            CPC();
        }

        // ---- P tile from smem adj + smem Er (no global latency) ------------
        {
            char* pb = sm + PS + s * 16384;
            const int4*   aj4 = (const int4*)(sm + AJ + s * 32768);
            const float4* er4 = (const float4*)(sm + ERS);
            #pragma unroll
            for (int rep = 0; rep < 4; ++rep) {
                int idx = t + rep * 512;       // 0..2047
                int row = idx >> 4, c4 = idx & 15;
                int4 av = aj4[idx];
                float2 el = elp[row];
                float4 ea = er4[tile * 32 + c4 * 2];
                float4 eb = er4[tile * 32 + c4 * 2 + 1];
                float q0 = el.x * ea.x; float p0 = (q0 > 1.f) ? q0 : el.y * ea.y;
                float q1 = el.x * ea.z; float p1 = (q1 > 1.f) ? q1 : el.y * ea.w;
                float q2 = el.x * eb.x; float p2 = (q2 > 1.f) ? q2 : el.y * eb.y;
                float q3 = el.x * eb.z; float p3 = (q3 > 1.f) ? q3 : el.y * eb.w;
                p0 = av.x ? p0 : 0.f;  p1 = av.y ? p1 : 0.f;
                p2 = av.z ? p2 : 0.f;  p3 = av.w ? p3 : 0.f;
                __half2 h01 = __floats2half2_rn(p0, p1);
                __half2 h23 = __floats2half2_rn(p2, p3);
                uint2 pk;
                pk.x = *(unsigned*)&h01;
                pk.y = *(unsigned*)&h23;
                *(uint2*)(pb + SWZ(row * 128 + c4 * 8)) = pk;
            }
        }
        __syncthreads();

        unsigned pbase = sb + PS + s * 16384;
        unsigned hbase = sb + HS + s * 32768;
        #pragma unroll
        for (int ks = 0; ks < 4; ++ks) {
            unsigned a0[4], a1[4];
            LDSM4(a0[0], a0[1], a0[2], a0[3],
                  pbase + SWZ((wm * 32      + (l & 15)) * 128 + ks * 32 + (l >> 4) * 16));
            LDSM4(a1[0], a1[1], a1[2], a1[3],
                  pbase + SWZ((wm * 32 + 16 + (l & 15)) * 128 + ks * 32 + (l >> 4) * 16));
            if (wn == 0) {
                MMA(sacc[0], a0[0], a0[1], a0[2], a0[3], ONESH, ONESH);
                MMA(sacc[1], a1[0], a1[1], a1[2], a1[3], ONESH, ONESH);
            }
            #pragma unroll
            for (int nb2 = 0; nb2 < 4; ++nb2) {
                unsigned b0, b1, b2, b3;
                LDSM4(b0, b1, b2, b3,
                      hbase + SWZ((wn * 64 + nb2 * 16 + (l & 15)) * 128 + ks * 32 + (l >> 4) * 16));
                MMA(acc[2*nb2][0],   a0[0], a0[1], a0[2], a0[3], b0, b2);
                MMA(acc[2*nb2][1],   a1[0], a1[1], a1[2], a1[3], b0, b2);
                MMA(acc[2*nb2+1][0], a0[0], a0[1], a0[2], a0[3], b1, b3);
                MMA(acc[2*nb2+1][1], a1[0], a1[1], a1[2], a1[3], b1, b3);
            }
        }
    }

    __syncthreads();
    if (wn == 0 && (l & 3) == 0) {
        int r = wm * 32 + (l >> 2);
        rsum[r]      = sacc[0][0];
        rsum[r + 8]  = sacc[0][2];
        rsum[r + 16] = sacc[1][0];
        rsum[r + 24] = sacc[1][2];
    }
    __syncthreads();

    #pragma unroll
    for (int mi = 0; mi < 2; ++mi) {
        int r0 = wm * 32 + mi * 16 + (l >> 2);
        float s0 = rsum[r0], s1 = rsum[r0 + 8];
        float inv0 = (s0 > 0.f) ? 1.f / s0 : 0.f;
        float inv1 = (s1 > 0.f) ? 1.f / s1 : 0.f;
        float* o0 = out + ((size_t)b * N_ + i0 + r0) * D_;
        float* o1 = o0 + 8 * D_;
        #pragma unroll
        for (int nb = 0; nb < 8; ++nb) {
            int c = wn * 64 + nb * 8 + 2 * (l & 3);
            *(float2*)(o0 + c) = make_float2(acc[nb][mi][0] * inv0,
                                             acc[nb][mi][1] * inv0);
            *(float2*)(o1 + c) = make_float2(acc[nb][mi][2] * inv1,
                                             acc[nb][mi][3] * inv1);
        }
    }
}

// ---------------------------------------------------------------------------
extern "C" void kernel_launch(void* const* d_in, const int* in_sizes, int n_in,
                              void* d_out, int out_size)
{
    const float* x   = (const float*)d_in[0];   // (8,2048,256) f32
    const int*   adj = (const int*)  d_in[1];   // (8,2048,2048) i32
    const float* W   = (const float*)d_in[2];   // (256,256) f32
    const float* a   = (const float*)d_in[3];   // (1,512) f32
    float*       out = (float*)d_out;           // (8,2048,256) f32

    cudaFuncSetAttribute(k_xh,   cudaFuncAttributeMaxDynamicSharedMemorySize, 98304);
    cudaFuncSetAttribute(k_aggr, cudaFuncAttributeMaxDynamicSharedMemorySize, 181760);

    k_prep <<<1, 256>>>(W, a);
    k_hlr  <<<(B_ * N_) / 8, 256>>>(x);
    k_xh   <<<dim3((B_ * N_) / 256, D_ / 64), 256, 98304>>>();
    k_aggr <<<dim3(N_ / 128, B_), 512, 181760>>>(adj, out);
}

// round 6
// speedup vs baseline: 3.8677x; 1.0341x over previous
#include <cuda_runtime.h>
#include <cuda_fp16.h>
#include <math.h>
#include <stdint.h>

#define B_ 8
#define N_ 2048
#define D_ 256

// ---------------------------------------------------------------------------
// helpers (baseline PTX only: cp.async / ldmatrix / mma.sync — compute_100 OK)
// ---------------------------------------------------------------------------
__device__ __forceinline__ unsigned smem_u32(const void* p) {
    unsigned a;
    asm("{ .reg .u64 t; cvta.to.shared.u64 t, %1; cvt.u32.u64 %0, t; }"
        : "=r"(a) : "l"(p));
    return a;
}
__device__ __forceinline__ int SWZ(int x) { return x ^ ((x >> 3) & 0x70); }

#define CP16(dst, src) \
    asm volatile("cp.async.cg.shared.global [%0], [%1], 16;" \
                 :: "r"((unsigned)(dst)), "l"(__cvta_generic_to_global(src)) : "memory")
#define CPC() asm volatile("cp.async.commit_group;" ::: "memory")
#define CPW0() asm volatile("cp.async.wait_group 0;" ::: "memory")
#define CPW1() asm volatile("cp.async.wait_group 1;" ::: "memory")

#define LDSM4(r0, r1, r2, r3, a) \
    asm volatile("ldmatrix.sync.aligned.m8n8.x4.shared.b16 {%0,%1,%2,%3}, [%4];" \
                 : "=r"(r0), "=r"(r1), "=r"(r2), "=r"(r3) : "r"((unsigned)(a)))

#define MMA(d, a0, a1, a2, a3, b0, b1) \
    asm volatile("mma.sync.aligned.m16n8k16.row.col.f32.f16.f16.f32 " \
                 "{%0,%1,%2,%3}, {%4,%5,%6,%7}, {%8,%9}, {%0,%1,%2,%3};" \
                 : "+f"((d)[0]), "+f"((d)[1]), "+f"((d)[2]), "+f"((d)[3]) \
                 : "r"(a0), "r"(a1), "r"(a2), "r"(a3), "r"(b0), "r"(b1))

// ---------------------------------------------------------------------------
// device globals (no allocation allowed)
// ---------------------------------------------------------------------------
__device__ float g_wl[D_];
__device__ float g_wr[D_];
__device__ __align__(16) float2 g_Elp[B_ * N_];   // (exp(hl), exp(0.2 hl))
__device__ __align__(16) float2 g_Erp[B_ * N_];   // (exp(hr), exp(0.2 hr))
__device__ __align__(16) __half g_Whf[D_ * D_];            // W fp16 row-major [o][k]
__device__ __align__(16) __half g_xh [B_ * N_ * D_];       // x fp16 row-major [m][k]
__device__ __align__(128) unsigned char g_ht[B_ * 32 * 32768]; // h^T fp16: [b][jt][d 256][j 64] swizzled

// ---------------- prep: wl/wr vectors + W fp16 conversion -------------------
__global__ void k_prep(const float* __restrict__ W, const float* __restrict__ a)
{
    int d = threadIdx.x;                      // 256 threads, 1 block
    float sl = 0.f, sr = 0.f;
    #pragma unroll 8
    for (int o = 0; o < D_; ++o) {
        float w = W[o * D_ + d];
        sl = fmaf(a[o],      w, sl);
        sr = fmaf(a[D_ + o], w, sr);
    }
    g_wl[d] = sl;
    g_wr[d] = sr;

    const float4* W4 = (const float4*)W;
    __half2* o = (__half2*)g_Whf;
    for (int q = 0; q < 64; ++q) {
        float4 v = W4[d * 64 + q];
        o[d * 128 + q * 2]     = __floats2half2_rn(v.x, v.y);
        o[d * 128 + q * 2 + 1] = __floats2half2_rn(v.z, v.w);
    }
}

// ---------------- k_hlr: hl/hr dots + factored exps + x->fp16 side-write ----
__global__ void k_hlr(const float* __restrict__ x)
{
    int m    = blockIdx.x * 8 + (threadIdx.x >> 5);
    int lane = threadIdx.x & 31;
    const float4* xr  = (const float4*)(x + (size_t)m * D_);
    const float4* wl4 = (const float4*)g_wl;
    const float4* wr4 = (const float4*)g_wr;
    float sl = 0.f, sr = 0.f;
    __half2* xo = (__half2*)(g_xh + (size_t)m * D_);
    #pragma unroll
    for (int q = 0; q < 2; ++q) {
        float4 xv = xr [lane + q * 32];
        float4 lv = wl4[lane + q * 32];
        float4 rv = wr4[lane + q * 32];
        sl += xv.x * lv.x + xv.y * lv.y + xv.z * lv.z + xv.w * lv.w;
        sr += xv.x * rv.x + xv.y * rv.y + xv.z * rv.z + xv.w * rv.w;
        xo[(lane + q * 32) * 2]     = __floats2half2_rn(xv.x, xv.y);
        xo[(lane + q * 32) * 2 + 1] = __floats2half2_rn(xv.z, xv.w);
    }
    #pragma unroll
    for (int off = 16; off > 0; off >>= 1) {
        sl += __shfl_xor_sync(0xFFFFFFFFu, sl, off);
        sr += __shfl_xor_sync(0xFFFFFFFFu, sr, off);
    }
    if (lane == 0) {
        g_Elp[m] = make_float2(expf(sl), expf(0.2f * sl));
        g_Erp[m] = make_float2(expf(sr), expf(0.2f * sr));
    }
}

// ---------------------------------------------------------------------------
// k_xh: h^T[d][j] = sum_k W[d][k] x[j][k]  (HMMA), smem-staged coalesced out
// CTA: 64 d x 256 j; warps m32 x n64; K loop 4 chunks of 64
// ---------------------------------------------------------------------------
__global__ __launch_bounds__(256) void k_xh()
{
    extern __shared__ char sm[];
    const int WS = 0, XS = 32768;
    unsigned sb = smem_u32(sm);
    int t = threadIdx.x, l = t & 31, w = t >> 5;
    int wm = w & 1, wn = w >> 1;
    int j0 = blockIdx.x * 256;
    int d0 = blockIdx.y * 64;

    #pragma unroll
    for (int q = 0; q < 8; ++q) {
        int idx = t + q * 256;
        int kc = idx >> 9, r = (idx >> 3) & 63, ch = idx & 7;
        CP16(sb + WS + kc * 8192 + SWZ(r * 128 + ch * 16),
             (const char*)g_Whf + (size_t)(d0 + r) * 512 + kc * 128 + ch * 16);
    }
    #pragma unroll
    for (int q = 0; q < 8; ++q) {
        int idx = t + q * 256, r = idx >> 3, ch = idx & 7;
        CP16(sb + XS + SWZ(r * 128 + ch * 16),
             (const char*)g_xh + (size_t)(j0 + r) * 512 + ch * 16);
    }
    CPC();

    float acc[8][2][4];
    #pragma unroll
    for (int i = 0; i < 8; ++i)
        #pragma unroll
        for (int m = 0; m < 2; ++m)
            #pragma unroll
            for (int c = 0; c < 4; ++c) acc[i][m][c] = 0.f;

    for (int kc = 0; kc < 4; ++kc) {
        if (kc < 3) {
            unsigned bbuf = sb + XS + ((kc + 1) & 1) * 32768;
            #pragma unroll
            for (int q = 0; q < 8; ++q) {
                int idx = t + q * 256, r = idx >> 3, ch = idx & 7;
                CP16(bbuf + SWZ(r * 128 + ch * 16),
                     (const char*)g_xh + (size_t)(j0 + r) * 512 + (kc + 1) * 128 + ch * 16);
            }
            CPC();
            CPW1();
        } else {
            CPW0();
        }
        __syncthreads();

        unsigned ab = sb + WS + kc * 8192;
        unsigned bb = sb + XS + (kc & 1) * 32768;
        #pragma unroll
        for (int ks = 0; ks < 4; ++ks) {
            unsigned a0[4], a1[4];
            LDSM4(a0[0], a0[1], a0[2], a0[3],
                  ab + SWZ((wm * 32      + (l & 15)) * 128 + ks * 32 + (l >> 4) * 16));
            LDSM4(a1[0], a1[1], a1[2], a1[3],
                  ab + SWZ((wm * 32 + 16 + (l & 15)) * 128 + ks * 32 + (l >> 4) * 16));
            #pragma unroll
            for (int nb2 = 0; nb2 < 4; ++nb2) {
                unsigned b0, b1, b2, b3;
                LDSM4(b0, b1, b2, b3,
                      bb + SWZ((wn * 64 + nb2 * 16 + (l & 15)) * 128 + ks * 32 + (l >> 4) * 16));
                MMA(acc[2*nb2][0],   a0[0], a0[1], a0[2], a0[3], b0, b2);
                MMA(acc[2*nb2][1],   a1[0], a1[1], a1[2], a1[3], b0, b2);
                MMA(acc[2*nb2+1][0], a0[0], a0[1], a0[2], a0[3], b1, b3);
                MMA(acc[2*nb2+1][1], a1[0], a1[1], a1[2], a1[3], b1, b3);
            }
        }
        __syncthreads();
    }

    // stage output (fp16, swizzled tile image) into smem, then coalesced copy
    #pragma unroll
    for (int mi = 0; mi < 2; ++mi) {
        int rd = wm * 32 + mi * 16 + (l >> 2);
        #pragma unroll
        for (int nb = 0; nb < 8; ++nb) {
            int jj = nb * 8 + 2 * (l & 3);
            __half2 v0 = __floats2half2_rn(acc[nb][mi][0], acc[nb][mi][1]);
            __half2 v1 = __floats2half2_rn(acc[nb][mi][2], acc[nb][mi][3]);
            *(__half2*)(sm + WS + wn * 8192 + SWZ( rd      * 128 + jj * 2)) = v0;
            *(__half2*)(sm + WS + wn * 8192 + SWZ((rd + 8) * 128 + jj * 2)) = v1;
        }
    }
    __syncthreads();

    int b   = j0 >> 11;
    int jt0 = (j0 & 2047) >> 6;
    #pragma unroll
    for (int q = 0; q < 8; ++q) {
        int c  = t + q * 256;                 // 2048 chunks x 16B
        int jt = c >> 9;
        int off = (c & 511) * 16;
        unsigned char* dst = g_ht + (size_t)(b * 32 + jt0 + jt) * 32768 + d0 * 128 + off;
        *(uint4*)dst = *(const uint4*)(sm + WS + c * 16);
    }
}

// ---------------------------------------------------------------------------
// k_aggr: fused masked-softmax aggregation (HMMA), phase-overlapped pipeline
// CTA 512 thr: i-tile M=128, warp tile m32 x n64 (wm, wn in 0..3), 32 j-tiles
// smem: H 3x32KB @0 | ADJ 2x32KB @98304 | P 2x16KB @163840 | ER 16KB @196608
//       | ELP 1KB @212992 | RSUM @214016   (total 214528)
// per tile t: barrier -> issue cp(t+2) -> P-compute(t+1) -> MMA(t) -> wait0
// ---------------------------------------------------------------------------
__global__ __launch_bounds__(512) void k_aggr(const int* __restrict__ adj,
                                              float* __restrict__ out)
{
    extern __shared__ char sm[];
    const int HS = 0, AJ = 98304, PS = 163840, ERS = 196608;
    const int ELP = 212992, RSUM = 214016;
    unsigned sb = smem_u32(sm);
    int t = threadIdx.x, l = t & 31, w = t >> 5;
    int wm = w & 3, wn = w >> 2;
    int b = blockIdx.y, i0 = blockIdx.x * 128;
    float2* elp  = (float2*)(sm + ELP);
    float*  rsum = (float*)(sm + RSUM);

    const unsigned char* hsrc = g_ht + (size_t)b * 32 * 32768;
    const int*           adjb = adj + ((size_t)b * N_ + i0) * N_;

    // G0: H(0) + ADJ(0) + Er row + Elp
    #pragma unroll
    for (int q = 0; q < 4; ++q) {
        int idx = t + q * 512;
        CP16(sb + HS + idx * 16, hsrc + idx * 16);
    }
    #pragma unroll
    for (int q = 0; q < 4; ++q) {
        int idx = t + q * 512;
        CP16(sb + AJ + idx * 16, adjb + ((size_t)(idx >> 4)) * N_ + (idx & 15) * 4);
    }
    #pragma unroll
    for (int q = 0; q < 2; ++q) {
        int idx = t + q * 512;
        CP16(sb + ERS + idx * 16, (const char*)(g_Erp + b * N_) + idx * 16);
    }
    if (t < 64) CP16(sb + ELP + t * 16, (const char*)(g_Elp + b * N_ + i0) + t * 16);
    CPC();
    // G1: H(1) + ADJ(1)
    #pragma unroll
    for (int q = 0; q < 4; ++q) {
        int idx = t + q * 512;
        CP16(sb + HS + 32768 + idx * 16, hsrc + 32768 + idx * 16);
    }
    #pragma unroll
    for (int q = 0; q < 4; ++q) {
        int idx = t + q * 512;
        CP16(sb + AJ + 32768 + idx * 16,
             adjb + 64 + ((size_t)(idx >> 4)) * N_ + (idx & 15) * 4);
    }
    CPC();
    CPW1();                 // G0 arrived
    __syncthreads();

    // P(0) (overlaps G1 flight)
    {
        char* pb = sm + PS;
        const int4*   aj4 = (const int4*)(sm + AJ);
        const float4* er4 = (const float4*)(sm + ERS);
        #pragma unroll
        for (int rep = 0; rep < 4; ++rep) {
            int idx = t + rep * 512;
            int row = idx >> 4, c4 = idx & 15;
            int4 av = aj4[idx];
            float2 el = elp[row];
            float4 ea = er4[c4 * 2];
            float4 eb = er4[c4 * 2 + 1];
            float q0 = el.x * ea.x; float p0 = (q0 > 1.f) ? q0 : el.y * ea.y;
            float q1 = el.x * ea.z; float p1 = (q1 > 1.f) ? q1 : el.y * ea.w;
            float q2 = el.x * eb.x; float p2 = (q2 > 1.f) ? q2 : el.y * eb.y;
            float q3 = el.x * eb.z; float p3 = (q3 > 1.f) ? q3 : el.y * eb.w;
            p0 = av.x ? p0 : 0.f;  p1 = av.y ? p1 : 0.f;
            p2 = av.z ? p2 : 0.f;  p3 = av.w ? p3 : 0.f;
            __half2 h01 = __floats2half2_rn(p0, p1);
            __half2 h23 = __floats2half2_rn(p2, p3);
            uint2 pk;
            pk.x = *(unsigned*)&h01;
            pk.y = *(unsigned*)&h23;
            *(uint2*)(pb + SWZ(row * 128 + c4 * 8)) = pk;
        }
    }
    CPW0();                 // G1 arrived

    float acc[8][2][4];
    #pragma unroll
    for (int i = 0; i < 8; ++i)
        #pragma unroll
        for (int m = 0; m < 2; ++m)
            #pragma unroll
            for (int c = 0; c < 4; ++c) acc[i][m][c] = 0.f;
    float sacc[2][4] = {{0.f,0.f,0.f,0.f},{0.f,0.f,0.f,0.f}};
    const unsigned ONESH = 0x3C003C00u;

    for (int tile = 0; tile < 32; ++tile) {
        __syncthreads();    // visibility of G(tile+1) + P(tile); buffer fences

        if (tile < 30) {    // issue G(tile+2)
            int nt = tile + 2;
            unsigned hdst = sb + HS + (nt % 3) * 32768;
            unsigned adst = sb + AJ + (nt & 1) * 32768;
            const unsigned char* hsr = hsrc + (size_t)nt * 32768;
            const int*           asr = adjb + nt * 64;
            #pragma unroll
            for (int q = 0; q < 4; ++q) {
                int idx = t + q * 512;
                CP16(hdst + idx * 16, hsr + idx * 16);
            }
            #pragma unroll
            for (int q = 0; q < 4; ++q) {
                int idx = t + q * 512;
                CP16(adst + idx * 16, asr + ((size_t)(idx >> 4)) * N_ + (idx & 15) * 4);
            }
            CPC();
        }

        if (tile < 31) {    // P(tile+1) — overlaps MMA(tile) via warp skew
            int nt = tile + 1;
            char* pb = sm + PS + (nt & 1) * 16384;
            const int4*   aj4 = (const int4*)(sm + AJ + (nt & 1) * 32768);
            const float4* er4 = (const float4*)(sm + ERS);
            #pragma unroll
            for (int rep = 0; rep < 4; ++rep) {
                int idx = t + rep * 512;
                int row = idx >> 4, c4 = idx & 15;
                int4 av = aj4[idx];
                float2 el = elp[row];
                float4 ea = er4[nt * 32 + c4 * 2];
                float4 eb = er4[nt * 32 + c4 * 2 + 1];
                float q0 = el.x * ea.x; float p0 = (q0 > 1.f) ? q0 : el.y * ea.y;
                float q1 = el.x * ea.z; float p1 = (q1 > 1.f) ? q1 : el.y * ea.w;
                float q2 = el.x * eb.x; float p2 = (q2 > 1.f) ? q2 : el.y * eb.y;
                float q3 = el.x * eb.z; float p3 = (q3 > 1.f) ? q3 : el.y * eb.w;
                p0 = av.x ? p0 : 0.f;  p1 = av.y ? p1 : 0.f;
                p2 = av.z ? p2 : 0.f;  p3 = av.w ? p3 : 0.f;
                __half2 h01 = __floats2half2_rn(p0, p1);
                __half2 h23 = __floats2half2_rn(p2, p3);
                uint2 pk;
                pk.x = *(unsigned*)&h01;
                pk.y = *(unsigned*)&h23;
                *(uint2*)(pb + SWZ(row * 128 + c4 * 8)) = pk;
            }
        }

        // MMA(tile)
        unsigned pbase = sb + PS + (tile & 1) * 16384;
        unsigned hbase = sb + HS + (tile % 3) * 32768;
        #pragma unroll
        for (int ks = 0; ks < 4; ++ks) {
            unsigned a0[4], a1[4];
            LDSM4(a0[0], a0[1], a0[2], a0[3],
                  pbase + SWZ((wm * 32      + (l & 15)) * 128 + ks * 32 + (l >> 4) * 16));
            LDSM4(a1[0], a1[1], a1[2], a1[3],
                  pbase + SWZ((wm * 32 + 16 + (l & 15)) * 128 + ks * 32 + (l >> 4) * 16));
            if (wn == 0) {
                MMA(sacc[0], a0[0], a0[1], a0[2], a0[3], ONESH, ONESH);
                MMA(sacc[1], a1[0], a1[1], a1[2], a1[3], ONESH, ONESH);
            }
            #pragma unroll
            for (int nb2 = 0; nb2 < 4; ++nb2) {
                unsigned b0, b1, b2, b3;
                LDSM4(b0, b1, b2, b3,
                      hbase + SWZ((wn * 64 + nb2 * 16 + (l & 15)) * 128 + ks * 32 + (l >> 4) * 16));
                MMA(acc[2*nb2][0],   a0[0], a0[1], a0[2], a0[3], b0, b2);
                MMA(acc[2*nb2][1],   a1[0], a1[1], a1[2], a1[3], b0, b2);
                MMA(acc[2*nb2+1][0], a0[0], a0[1], a0[2], a0[3], b1, b3);
                MMA(acc[2*nb2+1][1], a1[0], a1[1], a1[2], a1[3], b1, b3);
            }
        }
        CPW0();             // G(tile+2) arrived by iteration end
    }

    __syncthreads();
    if (wn == 0 && (l & 3) == 0) {
        int r = wm * 32 + (l >> 2);
        rsum[r]      = sacc[0][0];
        rsum[r + 8]  = sacc[0][2];
        rsum[r + 16] = sacc[1][0];
        rsum[r + 24] = sacc[1][2];
    }
    __syncthreads();

    #pragma unroll
    for (int mi = 0; mi < 2; ++mi) {
        int r0 = wm * 32 + mi * 16 + (l >> 2);
        float s0 = rsum[r0], s1 = rsum[r0 + 8];
        float inv0 = (s0 > 0.f) ? 1.f / s0 : 0.f;
        float inv1 = (s1 > 0.f) ? 1.f / s1 : 0.f;
        float* o0 = out + ((size_t)b * N_ + i0 + r0) * D_;
        float* o1 = o0 + 8 * D_;
        #pragma unroll
        for (int nb = 0; nb < 8; ++nb) {
            int c = wn * 64 + nb * 8 + 2 * (l & 3);
            *(float2*)(o0 + c) = make_float2(acc[nb][mi][0] * inv0,
                                             acc[nb][mi][1] * inv0);
            *(float2*)(o1 + c) = make_float2(acc[nb][mi][2] * inv1,
                                             acc[nb][mi][3] * inv1);
        }
    }
}

// ---------------------------------------------------------------------------
extern "C" void kernel_launch(void* const* d_in, const int* in_sizes, int n_in,
                              void* d_out, int out_size)
{
    const float* x   = (const float*)d_in[0];   // (8,2048,256) f32
    const int*   adj = (const int*)  d_in[1];   // (8,2048,2048) i32
    const float* W   = (const float*)d_in[2];   // (256,256) f32
    const float* a   = (const float*)d_in[3];   // (1,512) f32
    float*       out = (float*)d_out;           // (8,2048,256) f32

    cudaFuncSetAttribute(k_xh,   cudaFuncAttributeMaxDynamicSharedMemorySize, 98304);
    cudaFuncSetAttribute(k_aggr, cudaFuncAttributeMaxDynamicSharedMemorySize, 214528);

    k_prep <<<1, 256>>>(W, a);
    k_hlr  <<<(B_ * N_) / 8, 256>>>(x);
    k_xh   <<<dim3((B_ * N_) / 256, D_ / 64), 256, 98304>>>();
    k_aggr <<<dim3(N_ / 128, B_), 512, 214528>>>(adj, out);
}

// round 7
// speedup vs baseline: 4.1174x; 1.0646x over previous
#include <cuda_runtime.h>
#include <cuda_fp16.h>
#include <math.h>
#include <stdint.h>

#define B_ 8
#define N_ 2048
#define D_ 256

// ---------------------------------------------------------------------------
// helpers (baseline PTX only: cp.async / ldmatrix / mma.sync — compute_100 OK)
// ---------------------------------------------------------------------------
__device__ __forceinline__ unsigned smem_u32(const void* p) {
    unsigned a;
    asm("{ .reg .u64 t; cvta.to.shared.u64 t, %1; cvt.u32.u64 %0, t; }"
        : "=r"(a) : "l"(p));
    return a;
}
__device__ __forceinline__ int SWZ(int x) { return x ^ ((x >> 3) & 0x70); }

#define CP16(dst, src) \
    asm volatile("cp.async.cg.shared.global [%0], [%1], 16;" \
                 :: "r"((unsigned)(dst)), "l"(__cvta_generic_to_global(src)) : "memory")
#define CPC() asm volatile("cp.async.commit_group;" ::: "memory")
#define CPW0() asm volatile("cp.async.wait_group 0;" ::: "memory")
#define CPW1() asm volatile("cp.async.wait_group 1;" ::: "memory")

#define LDSM4(r0, r1, r2, r3, a) \
    asm volatile("ldmatrix.sync.aligned.m8n8.x4.shared.b16 {%0,%1,%2,%3}, [%4];" \
                 : "=r"(r0), "=r"(r1), "=r"(r2), "=r"(r3) : "r"((unsigned)(a)))

#define MMA(d, a0, a1, a2, a3, b0, b1) \
    asm volatile("mma.sync.aligned.m16n8k16.row.col.f32.f16.f16.f32 " \
                 "{%0,%1,%2,%3}, {%4,%5,%6,%7}, {%8,%9}, {%0,%1,%2,%3};" \
                 : "+f"((d)[0]), "+f"((d)[1]), "+f"((d)[2]), "+f"((d)[3]) \
                 : "r"(a0), "r"(a1), "r"(a2), "r"(a3), "r"(b0), "r"(b1))

// ---------------------------------------------------------------------------
// device globals (no allocation allowed)
// ---------------------------------------------------------------------------
__device__ float g_wl[D_];
__device__ float g_wr[D_];
__device__ __align__(16) float2 g_Elp[B_ * N_];   // (exp(hl), exp(0.2 hl))
__device__ __align__(16) float2 g_Erp[B_ * N_];   // (exp(hr), exp(0.2 hr))
__device__ __align__(16) __half g_Whf[D_ * D_];            // W fp16 row-major [o][k]
__device__ __align__(16) __half g_xh [B_ * N_ * D_];       // x fp16 row-major [m][k]
__device__ __align__(128) unsigned char g_ht[B_ * 32 * 32768]; // h^T fp16: [b][jt][d 256][j 64] swizzled

// ---------------- k_wlr: wl/wr vectors (1 block) ----------------------------
__global__ void k_wlr(const float* __restrict__ W, const float* __restrict__ a)
{
    int d = threadIdx.x;                      // 256 threads
    float sl = 0.f, sr = 0.f;
    #pragma unroll 8
    for (int o = 0; o < D_; ++o) {
        float w = W[o * D_ + d];
        sl = fmaf(a[o],      w, sl);
        sr = fmaf(a[D_ + o], w, sr);
    }
    g_wl[d] = sl;
    g_wr[d] = sr;
}

// ---------------- k_wconv: W f32 -> fp16, 16 blocks -------------------------
__global__ void k_wconv(const float* __restrict__ W)
{
    int i = blockIdx.x * 256 + threadIdx.x;   // 4096 threads, 16 f32 each
    const float4* W4 = (const float4*)W;
    __half2* o = (__half2*)g_Whf;
    #pragma unroll
    for (int q = 0; q < 4; ++q) {
        float4 v = W4[i * 4 + q];
        o[i * 8 + q * 2]     = __floats2half2_rn(v.x, v.y);
        o[i * 8 + q * 2 + 1] = __floats2half2_rn(v.z, v.w);
    }
}

// ---------------- k_hlr: hl/hr dots + factored exps + x->fp16 side-write ----
__global__ void k_hlr(const float* __restrict__ x)
{
    int m    = blockIdx.x * 8 + (threadIdx.x >> 5);
    int lane = threadIdx.x & 31;
    const float4* xr  = (const float4*)(x + (size_t)m * D_);
    const float4* wl4 = (const float4*)g_wl;
    const float4* wr4 = (const float4*)g_wr;
    float sl = 0.f, sr = 0.f;
    __half2* xo = (__half2*)(g_xh + (size_t)m * D_);
    #pragma unroll
    for (int q = 0; q < 2; ++q) {
        float4 xv = xr [lane + q * 32];
        float4 lv = wl4[lane + q * 32];
        float4 rv = wr4[lane + q * 32];
        sl += xv.x * lv.x + xv.y * lv.y + xv.z * lv.z + xv.w * lv.w;
        sr += xv.x * rv.x + xv.y * rv.y + xv.z * rv.z + xv.w * rv.w;
        xo[(lane + q * 32) * 2]     = __floats2half2_rn(xv.x, xv.y);
        xo[(lane + q * 32) * 2 + 1] = __floats2half2_rn(xv.z, xv.w);
    }
    #pragma unroll
    for (int off = 16; off > 0; off >>= 1) {
        sl += __shfl_xor_sync(0xFFFFFFFFu, sl, off);
        sr += __shfl_xor_sync(0xFFFFFFFFu, sr, off);
    }
    if (lane == 0) {
        g_Elp[m] = make_float2(expf(sl), expf(0.2f * sl));
        g_Erp[m] = make_float2(expf(sr), expf(0.2f * sr));
    }
}

// ---------------------------------------------------------------------------
// k_xh: h^T[d][j] = sum_k W[d][k] x[j][k]  (HMMA), smem-staged coalesced out
// CTA: 64 d x 256 j; warps m32 x n64; K loop 4 chunks of 64
// ---------------------------------------------------------------------------
__global__ __launch_bounds__(256) void k_xh()
{
    extern __shared__ char sm[];
    const int WS = 0, XS = 32768;
    unsigned sb = smem_u32(sm);
    int t = threadIdx.x, l = t & 31, w = t >> 5;
    int wm = w & 1, wn = w >> 1;
    int j0 = blockIdx.x * 256;
    int d0 = blockIdx.y * 64;

    #pragma unroll
    for (int q = 0; q < 8; ++q) {
        int idx = t + q * 256;
        int kc = idx >> 9, r = (idx >> 3) & 63, ch = idx & 7;
        CP16(sb + WS + kc * 8192 + SWZ(r * 128 + ch * 16),
             (const char*)g_Whf + (size_t)(d0 + r) * 512 + kc * 128 + ch * 16);
    }
    #pragma unroll
    for (int q = 0; q < 8; ++q) {
        int idx = t + q * 256, r = idx >> 3, ch = idx & 7;
        CP16(sb + XS + SWZ(r * 128 + ch * 16),
             (const char*)g_xh + (size_t)(j0 + r) * 512 + ch * 16);
    }
    CPC();

    float acc[8][2][4];
    #pragma unroll
    for (int i = 0; i < 8; ++i)
        #pragma unroll
        for (int m = 0; m < 2; ++m)
            #pragma unroll
            for (int c = 0; c < 4; ++c) acc[i][m][c] = 0.f;

    for (int kc = 0; kc < 4; ++kc) {
        if (kc < 3) {
            unsigned bbuf = sb + XS + ((kc + 1) & 1) * 32768;
            #pragma unroll
            for (int q = 0; q < 8; ++q) {
                int idx = t + q * 256, r = idx >> 3, ch = idx & 7;
                CP16(bbuf + SWZ(r * 128 + ch * 16),
                     (const char*)g_xh + (size_t)(j0 + r) * 512 + (kc + 1) * 128 + ch * 16);
            }
            CPC();
            CPW1();
        } else {
            CPW0();
        }
        __syncthreads();

        unsigned ab = sb + WS + kc * 8192;
        unsigned bb = sb + XS + (kc & 1) * 32768;
        #pragma unroll
        for (int ks = 0; ks < 4; ++ks) {
            unsigned a0[4], a1[4];
            LDSM4(a0[0], a0[1], a0[2], a0[3],
                  ab + SWZ((wm * 32      + (l & 15)) * 128 + ks * 32 + (l >> 4) * 16));
            LDSM4(a1[0], a1[1], a1[2], a1[3],
                  ab + SWZ((wm * 32 + 16 + (l & 15)) * 128 + ks * 32 + (l >> 4) * 16));
            #pragma unroll
            for (int nb2 = 0; nb2 < 4; ++nb2) {
                unsigned b0, b1, b2, b3;
                LDSM4(b0, b1, b2, b3,
                      bb + SWZ((wn * 64 + nb2 * 16 + (l & 15)) * 128 + ks * 32 + (l >> 4) * 16));
                MMA(acc[2*nb2][0],   a0[0], a0[1], a0[2], a0[3], b0, b2);
                MMA(acc[2*nb2][1],   a1[0], a1[1], a1[2], a1[3], b0, b2);
                MMA(acc[2*nb2+1][0], a0[0], a0[1], a0[2], a0[3], b1, b3);
                MMA(acc[2*nb2+1][1], a1[0], a1[1], a1[2], a1[3], b1, b3);
            }
        }
        __syncthreads();
    }

    // stage output (fp16, swizzled tile image) into smem, then coalesced copy
    #pragma unroll
    for (int mi = 0; mi < 2; ++mi) {
        int rd = wm * 32 + mi * 16 + (l >> 2);
        #pragma unroll
        for (int nb = 0; nb < 8; ++nb) {
            int jj = nb * 8 + 2 * (l & 3);
            __half2 v0 = __floats2half2_rn(acc[nb][mi][0], acc[nb][mi][1]);
            __half2 v1 = __floats2half2_rn(acc[nb][mi][2], acc[nb][mi][3]);
            *(__half2*)(sm + WS + wn * 8192 + SWZ( rd      * 128 + jj * 2)) = v0;
            *(__half2*)(sm + WS + wn * 8192 + SWZ((rd + 8) * 128 + jj * 2)) = v1;
        }
    }
    __syncthreads();

    int b   = j0 >> 11;
    int jt0 = (j0 & 2047) >> 6;
    #pragma unroll
    for (int q = 0; q < 8; ++q) {
        int c  = t + q * 256;                 // 2048 chunks x 16B
        int jt = c >> 9;
        int off = (c & 511) * 16;
        unsigned char* dst = g_ht + (size_t)(b * 32 + jt0 + jt) * 32768 + d0 * 128 + off;
        *(uint4*)dst = *(const uint4*)(sm + WS + c * 16);
    }
}

// ---------------------------------------------------------------------------
// k_aggr: fused masked-softmax aggregation (HMMA), depth-2 cp.async pipeline
// CTA 512 thr: i-tile M=128, warp tile m32 x n64 (wm, wn in 0..3), 32 j-tiles
// smem: H 3x32KB @0 | ADJ 2x32KB @98304 | P 2x16KB @163840 | ER 16KB @196608
//       | ELP 1KB @212992 | RSUM @214016   (total 214528)
// iter t: barrier -> issue G(t+2) -> wait_group1 (G(t+1) landed, G(t+2) in
//         flight) -> P(t+1) -> MMA(t)
// ---------------------------------------------------------------------------
__global__ __launch_bounds__(512) void k_aggr(const int* __restrict__ adj,
                                              float* __restrict__ out)
{
    extern __shared__ char sm[];
    const int HS = 0, AJ = 98304, PS = 163840, ERS = 196608;
    const int ELP = 212992, RSUM = 214016;
    unsigned sb = smem_u32(sm);
    int t = threadIdx.x, l = t & 31, w = t >> 5;
    int wm = w & 3, wn = w >> 2;
    int b = blockIdx.y, i0 = blockIdx.x * 128;
    float2* elp  = (float2*)(sm + ELP);
    float*  rsum = (float*)(sm + RSUM);

    const unsigned char* hsrc = g_ht + (size_t)b * 32 * 32768;
    const int*           adjb = adj + ((size_t)b * N_ + i0) * N_;

    // G0: H(0) + ADJ(0) + Er row + Elp
    #pragma unroll
    for (int q = 0; q < 4; ++q) {
        int idx = t + q * 512;
        CP16(sb + HS + idx * 16, hsrc + idx * 16);
    }
    #pragma unroll
    for (int q = 0; q < 4; ++q) {
        int idx = t + q * 512;
        CP16(sb + AJ + idx * 16, adjb + ((size_t)(idx >> 4)) * N_ + (idx & 15) * 4);
    }
    #pragma unroll
    for (int q = 0; q < 2; ++q) {
        int idx = t + q * 512;
        CP16(sb + ERS + idx * 16, (const char*)(g_Erp + b * N_) + idx * 16);
    }
    if (t < 64) CP16(sb + ELP + t * 16, (const char*)(g_Elp + b * N_ + i0) + t * 16);
    CPC();
    // G1: H(1) + ADJ(1)
    #pragma unroll
    for (int q = 0; q < 4; ++q) {
        int idx = t + q * 512;
        CP16(sb + HS + 32768 + idx * 16, hsrc + 32768 + idx * 16);
    }
    #pragma unroll
    for (int q = 0; q < 4; ++q) {
        int idx = t + q * 512;
        CP16(sb + AJ + 32768 + idx * 16,
             adjb + 64 + ((size_t)(idx >> 4)) * N_ + (idx & 15) * 4);
    }
    CPC();
    CPW1();                 // G0 arrived (G1 in flight)
    __syncthreads();

    // P(0) (overlaps G1 flight)
    {
        char* pb = sm + PS;
        const int4*   aj4 = (const int4*)(sm + AJ);
        const float4* er4 = (const float4*)(sm + ERS);
        #pragma unroll
        for (int rep = 0; rep < 4; ++rep) {
            int idx = t + rep * 512;
            int row = idx >> 4, c4 = idx & 15;
            int4 av = aj4[idx];
            float2 el = elp[row];
            float4 ea = er4[c4 * 2];
            float4 eb = er4[c4 * 2 + 1];
            float q0 = el.x * ea.x; float p0 = (q0 > 1.f) ? q0 : el.y * ea.y;
            float q1 = el.x * ea.z; float p1 = (q1 > 1.f) ? q1 : el.y * ea.w;
            float q2 = el.x * eb.x; float p2 = (q2 > 1.f) ? q2 : el.y * eb.y;
            float q3 = el.x * eb.z; float p3 = (q3 > 1.f) ? q3 : el.y * eb.w;
            p0 = av.x ? p0 : 0.f;  p1 = av.y ? p1 : 0.f;
            p2 = av.z ? p2 : 0.f;  p3 = av.w ? p3 : 0.f;
            __half2 h01 = __floats2half2_rn(p0, p1);
            __half2 h23 = __floats2half2_rn(p2, p3);
            uint2 pk;
            pk.x = *(unsigned*)&h01;
            pk.y = *(unsigned*)&h23;
            *(uint2*)(pb + SWZ(row * 128 + c4 * 8)) = pk;
        }
    }

    float acc[8][2][4];
    #pragma unroll
    for (int i = 0; i < 8; ++i)
        #pragma unroll
        for (int m = 0; m < 2; ++m)
            #pragma unroll
            for (int c = 0; c < 4; ++c) acc[i][m][c] = 0.f;
    float sacc[2][4] = {{0.f,0.f,0.f,0.f},{0.f,0.f,0.f,0.f}};
    const unsigned ONESH = 0x3C003C00u;

    for (int tile = 0; tile < 32; ++tile) {
        __syncthreads();    // P(tile) visible to all; buffer-reuse fence

        if (tile < 30) {    // issue G(tile+2), then wait for G(tile+1) only
            int nt = tile + 2;
            unsigned hdst = sb + HS + (nt % 3) * 32768;
            unsigned adst = sb + AJ + (nt & 1) * 32768;
            const unsigned char* hsr = hsrc + (size_t)nt * 32768;
            const int*           asr = adjb + nt * 64;
            #pragma unroll
            for (int q = 0; q < 4; ++q) {
                int idx = t + q * 512;
                CP16(hdst + idx * 16, hsr + idx * 16);
            }
            #pragma unroll
            for (int q = 0; q < 4; ++q) {
                int idx = t + q * 512;
                CP16(adst + idx * 16, asr + ((size_t)(idx >> 4)) * N_ + (idx & 15) * 4);
            }
            CPC();
            CPW1();         // G(tile+1) landed; G(tile+2) stays in flight
        } else {
            CPW0();         // drain tail
        }

        if (tile < 31) {    // P(tile+1) — overlaps MMA(tile) via warp skew
            int nt = tile + 1;
            char* pb = sm + PS + (nt & 1) * 16384;
            const int4*   aj4 = (const int4*)(sm + AJ + (nt & 1) * 32768);
            const float4* er4 = (const float4*)(sm + ERS);
            #pragma unroll
            for (int rep = 0; rep < 4; ++rep) {
                int idx = t + rep * 512;
                int row = idx >> 4, c4 = idx & 15;
                int4 av = aj4[idx];
                float2 el = elp[row];
                float4 ea = er4[nt * 32 + c4 * 2];
                float4 eb = er4[nt * 32 + c4 * 2 + 1];
                float q0 = el.x * ea.x; float p0 = (q0 > 1.f) ? q0 : el.y * ea.y;
                float q1 = el.x * ea.z; float p1 = (q1 > 1.f) ? q1 : el.y * ea.w;
                float q2 = el.x * eb.x; float p2 = (q2 > 1.f) ? q2 : el.y * eb.y;
                float q3 = el.x * eb.z; float p3 = (q3 > 1.f) ? q3 : el.y * eb.w;
                p0 = av.x ? p0 : 0.f;  p1 = av.y ? p1 : 0.f;
                p2 = av.z ? p2 : 0.f;  p3 = av.w ? p3 : 0.f;
                __half2 h01 = __floats2half2_rn(p0, p1);
                __half2 h23 = __floats2half2_rn(p2, p3);
                uint2 pk;
                pk.x = *(unsigned*)&h01;
                pk.y = *(unsigned*)&h23;
                *(uint2*)(pb + SWZ(row * 128 + c4 * 8)) = pk;
            }
        }

        // MMA(tile)
        unsigned pbase = sb + PS + (tile & 1) * 16384;
        unsigned hbase = sb + HS + (tile % 3) * 32768;
        #pragma unroll
        for (int ks = 0; ks < 4; ++ks) {
            unsigned a0[4], a1[4];
            LDSM4(a0[0], a0[1], a0[2], a0[3],
                  pbase + SWZ((wm * 32      + (l & 15)) * 128 + ks * 32 + (l >> 4) * 16));
            LDSM4(a1[0], a1[1], a1[2], a1[3],
                  pbase + SWZ((wm * 32 + 16 + (l & 15)) * 128 + ks * 32 + (l >> 4) * 16));
            if (wn == 0) {
                MMA(sacc[0], a0[0], a0[1], a0[2], a0[3], ONESH, ONESH);
                MMA(sacc[1], a1[0], a1[1], a1[2], a1[3], ONESH, ONESH);
            }
            #pragma unroll
            for (int nb2 = 0; nb2 < 4; ++nb2) {
                unsigned b0, b1, b2, b3;
                LDSM4(b0, b1, b2, b3,
                      hbase + SWZ((wn * 64 + nb2 * 16 + (l & 15)) * 128 + ks * 32 + (l >> 4) * 16));
                MMA(acc[2*nb2][0],   a0[0], a0[1], a0[2], a0[3], b0, b2);
                MMA(acc[2*nb2][1],   a1[0], a1[1], a1[2], a1[3], b0, b2);
                MMA(acc[2*nb2+1][0], a0[0], a0[1], a0[2], a0[3], b1, b3);
                MMA(acc[2*nb2+1][1], a1[0], a1[1], a1[2], a1[3], b1, b3);
            }
        }
    }

    __syncthreads();
    if (wn == 0 && (l & 3) == 0) {
        int r = wm * 32 + (l >> 2);
        rsum[r]      = sacc[0][0];
        rsum[r + 8]  = sacc[0][2];
        rsum[r + 16] = sacc[1][0];
        rsum[r + 24] = sacc[1][2];
    }
    __syncthreads();

    #pragma unroll
    for (int mi = 0; mi < 2; ++mi) {
        int r0 = wm * 32 + mi * 16 + (l >> 2);
        float s0 = rsum[r0], s1 = rsum[r0 + 8];
        float inv0 = (s0 > 0.f) ? 1.f / s0 : 0.f;
        float inv1 = (s1 > 0.f) ? 1.f / s1 : 0.f;
        float* o0 = out + ((size_t)b * N_ + i0 + r0) * D_;
        float* o1 = o0 + 8 * D_;
        #pragma unroll
        for (int nb = 0; nb < 8; ++nb) {
            int c = wn * 64 + nb * 8 + 2 * (l & 3);
            *(float2*)(o0 + c) = make_float2(acc[nb][mi][0] * inv0,
                                             acc[nb][mi][1] * inv0);
            *(float2*)(o1 + c) = make_float2(acc[nb][mi][2] * inv1,
                                             acc[nb][mi][3] * inv1);
        }
    }
}

// ---------------------------------------------------------------------------
extern "C" void kernel_launch(void* const* d_in, const int* in_sizes, int n_in,
                              void* d_out, int out_size)
{
    const float* x   = (const float*)d_in[0];   // (8,2048,256) f32
    const int*   adj = (const int*)  d_in[1];   // (8,2048,2048) i32
    const float* W   = (const float*)d_in[2];   // (256,256) f32
    const float* a   = (const float*)d_in[3];   // (1,512) f32
    float*       out = (float*)d_out;           // (8,2048,256) f32

    cudaFuncSetAttribute(k_xh,   cudaFuncAttributeMaxDynamicSharedMemorySize, 98304);
    cudaFuncSetAttribute(k_aggr, cudaFuncAttributeMaxDynamicSharedMemorySize, 214528);

    k_wlr  <<<1, 256>>>(W, a);
    k_wconv<<<16, 256>>>(W);
    k_hlr  <<<(B_ * N_) / 8, 256>>>(x);
    k_xh   <<<dim3((B_ * N_) / 256, D_ / 64), 256, 98304>>>();
    k_aggr <<<dim3(N_ / 128, B_), 512, 214528>>>(adj, out);
}